// round 15
// baseline (speedup 1.0000x reference)
#include <cuda_runtime.h>
#include <cstdint>
#include <math.h>

// Problem dims
#define T_SEQ 512
#define BATCH 8
#define HID   512
#define EMB   256
#define VOCAB 32000
#define M_TOT (BATCH*T_SEQ)   // 4096
#define G4H   (4*HID)         // 2048

// ---------------- scratch (device globals; no allocation allowed) -----------
__device__ float    g_x0 [M_TOT*EMB];      // gathered embeddings
__device__ float    g_xg [M_TOT*G4H];      // layer0 input-gate contributions
__device__ float    g_hs1[M_TOT*HID];      // layer1 outputs (FC input)
__device__ float    g_h0 [4][HID*BATCH];   // RING-buffered h0 (depth 4), [n][b]
__device__ float    g_h1 [2][HID*BATCH];   // double-buffered h1
__device__ unsigned g_flags0[64*8];        // per-CTA step flags, 32B stride
__device__ unsigned g_flags1[64*8];
__device__ unsigned g_abort;               // safety abort flag

// ---------------- embedding gather ------------------------------------------
__global__ void gather_kernel(const int* __restrict__ ids,
                              const float* __restrict__ emb) {
    int m  = blockIdx.x;
    int id = ids[m];
    const float4* s = (const float4*)(emb + (size_t)id * EMB);
    float4*       d = (float4*)(g_x0 + (size_t)m * EMB);
    d[threadIdx.x] = s[threadIdx.x];
}

// ---------------- flag reset (before the recurrence) ------------------------
__global__ void reset_kernel() {
    int i = threadIdx.x;
    if (i < 64 * 8) { g_flags0[i] = 0u; g_flags1[i] = 0u; }
    if (i == 0) g_abort = 0u;
}

// ---------------- tf32 mma GEMM (static smem, known-good) -------------------
__device__ __forceinline__ float f2tf32(float x) {
    float r;
    asm("cvt.rna.tf32.f32 %0, %1;" : "=f"(r) : "f"(x));
    return r;
}

__global__ void __launch_bounds__(256)
gemm_tf32_kernel(const float* __restrict__ A, const float* __restrict__ B,
                 const float* __restrict__ bias1, const float* __restrict__ bias2,
                 float* __restrict__ C, int M, int N, int K)
{
    __shared__ float As[128][36];
    __shared__ float Bs[128][36];

    int tid  = threadIdx.x;
    int warp = tid >> 5, lane = tid & 31;
    int wm   = warp >> 2, wn = warp & 3;
    int grp  = lane >> 2, tig = lane & 3;

    int mBase = blockIdx.y << 7;
    int nBase = blockIdx.x << 7;

    float acc[4][4][4];
    #pragma unroll
    for (int a = 0; a < 4; a++)
        #pragma unroll
        for (int b = 0; b < 4; b++)
            #pragma unroll
            for (int c = 0; c < 4; c++) acc[a][b][c] = 0.f;

    for (int k0 = 0; k0 < K; k0 += 32) {
        #pragma unroll
        for (int i = 0; i < 4; i++) {
            int f  = tid + (i << 8);
            int m  = f >> 3;
            int k4 = (f & 7) << 2;
            float4 va = *(const float4*)(A + (size_t)(mBase + m) * K + k0 + k4);
            *(float4*)&As[m][k4] = make_float4(f2tf32(va.x), f2tf32(va.y),
                                               f2tf32(va.z), f2tf32(va.w));
            float4 vb = *(const float4*)(B + (size_t)(nBase + m) * K + k0 + k4);
            *(float4*)&Bs[m][k4] = make_float4(f2tf32(vb.x), f2tf32(vb.y),
                                               f2tf32(vb.z), f2tf32(vb.w));
        }
        __syncthreads();

        #pragma unroll
        for (int kk = 0; kk < 32; kk += 8) {
            uint32_t af[4][4], bf[4][2];
            #pragma unroll
            for (int mi = 0; mi < 4; mi++) {
                int r = (wm << 6) + (mi << 4);
                af[mi][0] = __float_as_uint(As[r + grp    ][kk + tig    ]);
                af[mi][1] = __float_as_uint(As[r + grp + 8][kk + tig    ]);
                af[mi][2] = __float_as_uint(As[r + grp    ][kk + tig + 4]);
                af[mi][3] = __float_as_uint(As[r + grp + 8][kk + tig + 4]);
            }
            #pragma unroll
            for (int ni = 0; ni < 4; ni++) {
                int cN = (wn << 5) + (ni << 3);
                bf[ni][0] = __float_as_uint(Bs[cN + grp][kk + tig    ]);
                bf[ni][1] = __float_as_uint(Bs[cN + grp][kk + tig + 4]);
            }
            #pragma unroll
            for (int mi = 0; mi < 4; mi++)
                #pragma unroll
                for (int ni = 0; ni < 4; ni++)
                    asm volatile(
                        "mma.sync.aligned.m16n8k8.row.col.f32.tf32.tf32.f32 "
                        "{%0,%1,%2,%3}, {%4,%5,%6,%7}, {%8,%9}, {%0,%1,%2,%3};"
                        : "+f"(acc[mi][ni][0]), "+f"(acc[mi][ni][1]),
                          "+f"(acc[mi][ni][2]), "+f"(acc[mi][ni][3])
                        : "r"(af[mi][0]), "r"(af[mi][1]),
                          "r"(af[mi][2]), "r"(af[mi][3]),
                          "r"(bf[ni][0]), "r"(bf[ni][1]));
        }
        __syncthreads();
    }

    #pragma unroll
    for (int mi = 0; mi < 4; mi++) {
        int mrow = mBase + (wm << 6) + (mi << 4) + grp;
        #pragma unroll
        for (int ni = 0; ni < 4; ni++) {
            int nc = nBase + (wn << 5) + (ni << 3) + (tig << 1);
            float b0 = bias1[nc], b1 = bias1[nc + 1];
            if (bias2) { b0 += bias2[nc]; b1 += bias2[nc + 1]; }
            float2 v0 = make_float2(acc[mi][ni][0] + b0, acc[mi][ni][1] + b1);
            float2 v1 = make_float2(acc[mi][ni][2] + b0, acc[mi][ni][3] + b1);
            *(float2*)(C + (size_t)mrow       * N + nc) = v0;
            *(float2*)(C + (size_t)(mrow + 8) * N + nc) = v1;
        }
    }
}

// ---------------- fast activations (MUFU ex2/rcp; rel err ~1e-6) ------------
__device__ __forceinline__ float fast_sig(float x) {
    float e, r;
    asm("ex2.approx.ftz.f32 %0, %1;" : "=f"(e) : "f"(-1.4426950408889634f * x));
    asm("rcp.approx.ftz.f32 %0, %1;" : "=f"(r) : "f"(1.f + e));
    return r;
}
__device__ __forceinline__ float fast_tanh(float x) {
    float e, r;
    asm("ex2.approx.ftz.f32 %0, %1;" : "=f"(e) : "f"(-2.8853900817779268f * x));
    asm("rcp.approx.ftz.f32 %0, %1;" : "=f"(r) : "f"(1.f + e));
    return 2.f * r - 1.f;
}

// ---------------- bounded acquire-poll on one flag (hang-proof) -------------
__device__ __forceinline__ int poll_flag(unsigned* p, unsigned target) {
    volatile unsigned* abt = (volatile unsigned*)&g_abort;
    unsigned it = 0;
    for (;;) {
        unsigned v;
        asm volatile("ld.acquire.gpu.global.u32 %0, [%1];" : "=r"(v) : "l"(p));
        if (v >= target) return 0;
        if ((++it & 63u) == 0u) {
            if (*abt) return 1;
            if (it > (1u << 22)) { atomicExch(&g_abort, 1u); return 1; }
            __nanosleep(32);
        }
    }
}

// ---------------- persistent decoupled-layer LSTM, tensor-core dot -----------
// 128 CTAs co-resident. CTAs 0..63: layer0; 64..127: layer1; 8 hidden units
// (32 gate rows) per CTA. Per-layer distributed flag barrier: CTA j releases
// flags[j]; each waiter thread acquire-polls exactly the flags of the CTAs
// whose h data it copies (collectively all 64 + syncthreads = full barrier).
// Dot = mma.m16n8k8 tf32: warp w covers a k-slice, partials in Pt, reduced by
// the 64 act threads. h0 ring depth 4 lets L0 run ahead of L1.
#define NCTA_L 64
#define WST0 516
#define WST1 1036

__global__ void __launch_bounds__(256)
lstm_persist_kernel(const float* __restrict__ Whh0, const float* __restrict__ xg,
                    const float* __restrict__ Whh1, const float* __restrict__ Wih1,
                    const float* __restrict__ bi1,  const float* __restrict__ bh1,
                    float* __restrict__ hs1)
{
    extern __shared__ float sm[];
    __shared__ int s_ab;
    int tid  = threadIdx.x;
    bool isL1 = blockIdx.x >= 64;
    int cta  = isL1 ? blockIdx.x - 64 : blockIdx.x;
    int base = cta << 3;

    const int WST = isL1 ? WST1 : WST0;
    float* Ws = sm;                    // 32 rows x WST (tf32 values)
    float* Hb = sm + 32 * WST;         //  8 x WST (h, tf32 values)
    float* Pt = Hb + 8 * WST;          // 256 x 9 k-partials
    float* Cs = Pt + 256 * 9;          // 64 cell states

    // ---- one-time staging (convert W to tf32) ----
    if (!isL1) {
        #pragma unroll 4
        for (int i = tid; i < 4096; i += 256) {
            int r = i >> 7, c4 = (i & 127) << 2;
            int g = r >> 3, u = r & 7;
            float4 v = *(const float4*)(Whh0 + (size_t)((g << 9) + base + u) * HID + c4);
            *(float4*)(Ws + r * WST0 + c4) =
                make_float4(f2tf32(v.x), f2tf32(v.y), f2tf32(v.z), f2tf32(v.w));
        }
    } else {
        #pragma unroll 4
        for (int i = tid; i < 8192; i += 256) {
            int r = i >> 8, c4 = (i & 255) << 2;
            int g = r >> 3, u = r & 7;
            const float* src = (c4 < 512) ? Whh1 : Wih1;
            int col = (c4 < 512) ? c4 : c4 - 512;
            float4 v = *(const float4*)(src + (size_t)((g << 9) + base + u) * HID + col);
            *(float4*)(Ws + r * WST1 + c4) =
                make_float4(f2tf32(v.x), f2tf32(v.y), f2tf32(v.z), f2tf32(v.w));
        }
    }
    for (int i = tid; i < 8 * WST; i += 256) Hb[i] = 0.f;
    if (tid < 64) Cs[tid] = 0.f;
    if (tid == 0) s_ab = 0;

    int au = tid >> 3, ab_ = tid & 7;        // act-thread coords (tid < 64)
    float bias_g[4] = {0.f, 0.f, 0.f, 0.f};
    if (isL1 && tid < 64) {
        #pragma unroll
        for (int g = 0; g < 4; g++) {
            int row = (g << 9) + base + au;
            bias_g[g] = __ldg(bi1 + row) + __ldg(bh1 + row);
        }
    }
    __syncthreads();

    // mma mapping: warp w = k-slice; lane: grp = lane>>2 (row/batch group),
    // tig = lane&3 (k sub-col). Fragment indices identical to the GEMM.
    int w    = tid >> 5, lane = tid & 31;
    int grp  = lane >> 2, tig = lane & 3;
    int kpw  = isL1 ? 16 : 8;                // mma k-steps per warp
    int kb0  = w * kpw * 8;                  // starting float col

    unsigned* myflag   = (isL1 ? g_flags1 : g_flags0) + cta * 8;
    unsigned* ownflags = isL1 ? g_flags1 : g_flags0;

    // copy/refresh source CTAs for this thread: {tid>>4 + 16q}, chunks {tid+256q}
    int src_cta = tid >> 4;

    for (int t = 0; t < T_SEQ; t++) {
        int ab = 0;

        if (!isL1) {
            // ring guard: h0 slot t%4 consumed by ALL L1 CTAs (step t-4 done)
            if (t >= 4 && tid < 64)
                ab |= poll_flag(&g_flags1[tid * 8], (unsigned)(t - 3));
        } else {
            // wait for h0_t from the CTAs whose data this thread copies
            #pragma unroll
            for (int q = 0; q < 4; q++)
                ab |= poll_flag(&g_flags0[(src_cta + 16 * q) * 8], (unsigned)(t + 1));
            // copy h0_t into Hb cols [512,1024), tf32-converted
            const float4* s04 = (const float4*)g_h0[t & 3];
            #pragma unroll
            for (int q = 0; q < 4; q++) {
                int i = tid + (q << 8);
                float4 v = __ldcg(s04 + i);
                int k = (i >> 1) + 512, b0 = (i & 1) << 2;
                Hb[(b0    ) * WST1 + k] = f2tf32(v.x);
                Hb[(b0 + 1) * WST1 + k] = f2tf32(v.y);
                Hb[(b0 + 2) * WST1 + k] = f2tf32(v.z);
                Hb[(b0 + 3) * WST1 + k] = f2tf32(v.w);
            }
            if (ab) s_ab = 1;
            __syncthreads();                 // sync0: Hb [h1|h0] ready
        }

        // act threads prefetch xg early (L0)
        float xv0 = 0.f, xv1 = 0.f, xv2 = 0.f, xv3 = 0.f;
        if (!isL1 && tid < 64) {
            const float* xr = xg + (size_t)((ab_ << 9) + t) * G4H + base + au;
            xv0 = __ldg(xr);        xv1 = __ldg(xr + 512);
            xv2 = __ldg(xr + 1024); xv3 = __ldg(xr + 1536);
        }

        {   // ---- tensor-core dot: D[32 rows x 8 batch] over warp's k-slice ----
            float acc[2][4];
            #pragma unroll
            for (int m = 0; m < 2; m++)
                #pragma unroll
                for (int d = 0; d < 4; d++) acc[m][d] = 0.f;

            for (int ks = 0; ks < kpw; ks++) {
                int kk = kb0 + (ks << 3);
                uint32_t b0 = __float_as_uint(Hb[grp * WST + kk + tig    ]);
                uint32_t b1 = __float_as_uint(Hb[grp * WST + kk + tig + 4]);
                #pragma unroll
                for (int m = 0; m < 2; m++) {
                    int r = m << 4;
                    uint32_t a0 = __float_as_uint(Ws[(r + grp    ) * WST + kk + tig    ]);
                    uint32_t a1 = __float_as_uint(Ws[(r + grp + 8) * WST + kk + tig    ]);
                    uint32_t a2 = __float_as_uint(Ws[(r + grp    ) * WST + kk + tig + 4]);
                    uint32_t a3 = __float_as_uint(Ws[(r + grp + 8) * WST + kk + tig + 4]);
                    asm volatile(
                        "mma.sync.aligned.m16n8k8.row.col.f32.tf32.tf32.f32 "
                        "{%0,%1,%2,%3}, {%4,%5,%6,%7}, {%8,%9}, {%0,%1,%2,%3};"
                        : "+f"(acc[m][0]), "+f"(acc[m][1]),
                          "+f"(acc[m][2]), "+f"(acc[m][3])
                        : "r"(a0), "r"(a1), "r"(a2), "r"(a3),
                          "r"(b0), "r"(b1));
                }
            }
            #pragma unroll
            for (int m = 0; m < 2; m++) {
                int r0 = (m << 4) + grp;
                Pt[((r0    ) * 8 + (tig << 1)    ) * 9 + w] = acc[m][0];
                Pt[((r0    ) * 8 + (tig << 1) + 1) * 9 + w] = acc[m][1];
                Pt[((r0 + 8) * 8 + (tig << 1)    ) * 9 + w] = acc[m][2];
                Pt[((r0 + 8) * 8 + (tig << 1) + 1) * 9 + w] = acc[m][3];
            }
        }
        if (ab) s_ab = 1;
        __syncthreads();                 // sync1: Pt complete; ring guard done

        if (tid < 64) {                  // fused reduce + act + publish
            float gs[4];
            #pragma unroll
            for (int g = 0; g < 4; g++) {
                int slot = (((g << 3) + au) << 3) + ab_;
                float s = 0.f;
                #pragma unroll
                for (int k = 0; k < 8; k++) s += Pt[slot * 9 + k];
                gs[g] = s;
            }
            if (!isL1) { gs[0] += xv0; gs[1] += xv1; gs[2] += xv2; gs[3] += xv3; }
            else       { gs[0] += bias_g[0]; gs[1] += bias_g[1];
                         gs[2] += bias_g[2]; gs[3] += bias_g[3]; }
            float i_ = fast_sig(gs[0]);
            float f_ = fast_sig(gs[1]);
            float gg = fast_tanh(gs[2]);
            float o_ = fast_sig(gs[3]);
            float c  = f_ * Cs[tid] + i_ * gg;
            Cs[tid]  = c;
            float h  = o_ * fast_tanh(c);
            if (!isL1) {
                g_h0[t & 3][(base << 3) + tid] = h;
            } else {
                g_h1[t & 1][(base << 3) + tid] = h;
                hs1[(size_t)((ab_ << 9) + t) * HID + base + au] = h;
            }
        }
        __syncthreads();                 // sync2: h stores CTA-wide HB

        if (tid == 0)                    // release own flag = t+1
            asm volatile("st.release.gpu.global.u32 [%0], %1;"
                         :: "l"(myflag), "r"((unsigned)(t + 1)) : "memory");

        // own-layer barrier + refresh: poll exactly the source CTAs, copy
        #pragma unroll
        for (int q = 0; q < 4; q++)
            ab |= poll_flag(&ownflags[(src_cta + 16 * q) * 8], (unsigned)(t + 1));

        if (!isL1) {
            const float4* s4 = (const float4*)g_h0[t & 3];
            #pragma unroll
            for (int q = 0; q < 4; q++) {
                int i = tid + (q << 8);
                float4 v = __ldcg(s4 + i);
                int k = i >> 1, b0 = (i & 1) << 2;
                Hb[(b0    ) * WST0 + k] = f2tf32(v.x);
                Hb[(b0 + 1) * WST0 + k] = f2tf32(v.y);
                Hb[(b0 + 2) * WST0 + k] = f2tf32(v.z);
                Hb[(b0 + 3) * WST0 + k] = f2tf32(v.w);
            }
        } else {
            const float4* s14 = (const float4*)g_h1[t & 1];
            #pragma unroll
            for (int q = 0; q < 4; q++) {
                int i = tid + (q << 8);
                float4 v = __ldcg(s14 + i);
                int k = i >> 1, b0 = (i & 1) << 2;
                Hb[(b0    ) * WST1 + k] = f2tf32(v.x);
                Hb[(b0 + 1) * WST1 + k] = f2tf32(v.y);
                Hb[(b0 + 2) * WST1 + k] = f2tf32(v.z);
                Hb[(b0 + 3) * WST1 + k] = f2tf32(v.w);
            }
        }
        if (ab) s_ab = 1;
        __syncthreads();                 // sync3: Hb ready; s_ab stable
        if (s_ab) return;                // uniform, hang-proof exit
    }
}

// ---------------- launch -----------------------------------------------------
extern "C" void kernel_launch(void* const* d_in, const int* in_sizes, int n_in,
                              void* d_out, int out_size)
{
    (void)in_sizes; (void)n_in; (void)out_size;
    const int*   ids   = (const int*)d_in[0];
    const float* emb   = (const float*)d_in[1];
    const float* W_ih0 = (const float*)d_in[2];
    const float* W_hh0 = (const float*)d_in[3];
    const float* b_ih0 = (const float*)d_in[4];
    const float* b_hh0 = (const float*)d_in[5];
    const float* W_ih1 = (const float*)d_in[6];
    const float* W_hh1 = (const float*)d_in[7];
    const float* b_ih1 = (const float*)d_in[8];
    const float* b_hh1 = (const float*)d_in[9];
    const float* W_fc  = (const float*)d_in[10];
    const float* b_fc  = (const float*)d_in[11];
    float* out = (float*)d_out;

    float *x0, *xgp, *hs1;
    cudaGetSymbolAddress((void**)&x0,  g_x0);
    cudaGetSymbolAddress((void**)&xgp, g_xg);
    cudaGetSymbolAddress((void**)&hs1, g_hs1);

    // dynamic smem (L1 branch): 40*WST1 + 256*9 + 64 floats
    const int per_smem = (40 * WST1 + 256 * 9 + 64) * (int)sizeof(float); // 175232
    cudaFuncSetAttribute(lstm_persist_kernel,
                         cudaFuncAttributeMaxDynamicSharedMemorySize, per_smem);

    // 1) gather embeddings
    gather_kernel<<<M_TOT, EMB / 4>>>(ids, emb);

    // 2) xg = x0 @ W_ih0^T + b_ih0 + b_hh0     [4096 x 2048], K=256
    gemm_tf32_kernel<<<dim3(G4H / 128, M_TOT / 128), 256>>>(
        x0, W_ih0, b_ih0, b_hh0, xgp, M_TOT, G4H, EMB);

    // 3) reset flags
    reset_kernel<<<1, 512>>>();

    // 4) both LSTM layers, decoupled, in ONE persistent launch
    lstm_persist_kernel<<<2 * NCTA_L, 256, per_smem>>>(
        W_hh0, xgp, W_hh1, W_ih1, b_ih1, b_hh1, hs1);

    // 5) logits = hs1 @ W_fc^T + b_fc          [4096 x 32000], K=512
    gemm_tf32_kernel<<<dim3(VOCAB / 128, M_TOT / 128), 256>>>(
        hs1, W_fc, b_fc, nullptr, out, M_TOT, VOCAB, HID);
}